// round 12
// baseline (speedup 1.0000x reference)
#include <cuda_runtime.h>
#include <cuda_fp16.h>
#include <cstdint>
#include <math.h>

// Problem constants
#define NB 16384
#define NC 5
#define NH 256
#define NV 512
#define NCV 2560
#define NBH 4194304
#define NBCV 41943040u
#define TINYF 1.17549435082228751e-38f

// ---------------- scratch (static device globals) ----------------
__device__ __half   g_hb[(size_t)NB * NH];      // h fp16 (A for sample_v, K=256)
__device__ uint8_t  g_idx[(size_t)NB * NV];     // current v category per (b,v)
__device__ __half   g_Acomp[(size_t)NB * 1280]; // 2:4-compressed one-hot A (K'=2560 -> 1280)
__device__ uint32_t g_meta[(size_t)NB * 80];    // sparsity metadata, 1 word per (row, k32 chunk)
__device__ __half   g_Wv2[2][NCV * NH];         // [split][v*5+c][h]   (B for sample_v)
__device__ __half   g_Wh2[2][NH * NCV];         // [split][h][v*5+c]   (B for sample_h)

// ---------------- threefry2x32 (bit-exact with JAX, partitionable) ----------------
__host__ __device__ __forceinline__ uint32_t rotl32(uint32_t x, int r) {
#ifdef __CUDA_ARCH__
    return __funnelshift_l(x, x, r);
#else
    return (x << r) | (x >> (32 - r));
#endif
}

__host__ __device__ inline void threefry(uint32_t k0, uint32_t k1,
                                         uint32_t x0, uint32_t x1,
                                         uint32_t& o0, uint32_t& o1) {
    uint32_t k2 = k0 ^ k1 ^ 0x1BD11BDAu;
#define TFR(r) { x0 += x1; x1 = rotl32(x1, (r)); x1 ^= x0; }
    x0 += k0; x1 += k1;
    TFR(13) TFR(15) TFR(26) TFR(6)   x0 += k1; x1 += k2 + 1u;
    TFR(17) TFR(29) TFR(16) TFR(24)  x0 += k2; x1 += k0 + 2u;
    TFR(13) TFR(15) TFR(26) TFR(6)   x0 += k0; x1 += k1 + 3u;
    TFR(17) TFR(29) TFR(16) TFR(24)  x0 += k1; x1 += k2 + 4u;
    TFR(13) TFR(15) TFR(26) TFR(6)   x0 += k2; x1 += k0 + 5u;
#undef TFR
    o0 = x0; o1 = x1;
}

__device__ __forceinline__ uint32_t rand_bits(uint32_t k0, uint32_t k1, uint32_t i) {
    uint32_t a, b;
    threefry(k0, k1, 0u, i, a, b);
    return a ^ b;
}

__device__ __forceinline__ float bits_to_unit(uint32_t bits) {
    return __fadd_rn(__uint_as_float((bits >> 9) | 0x3f800000u), -1.0f);
}

// ---------------- small helpers ----------------
__device__ __forceinline__ uint32_t smem_u32(const void* p) {
    uint32_t a;
    asm("{ .reg .u64 t; cvta.to.shared.u64 t, %1; cvt.u32.u64 %0, t; }" : "=r"(a) : "l"(p));
    return a;
}

__device__ __forceinline__ void cp16(uint32_t s, const void* g) {
    asm volatile("cp.async.cg.shared.global [%0], [%1], 16;" :: "r"(s), "l"(g));
}
__device__ __forceinline__ void cp4(uint32_t s, const void* g) {
    asm volatile("cp.async.ca.shared.global [%0], [%1], 4;" :: "r"(s), "l"(g));
}
#define CP_COMMIT() asm volatile("cp.async.commit_group;" ::: "memory")
#define CP_WAIT(n)  asm volatile("cp.async.wait_group %0;" :: "n"(n) : "memory")

__device__ __forceinline__ void ldmx4(uint32_t* r, uint32_t addr) {
    asm volatile("ldmatrix.sync.aligned.m8n8.x4.shared.b16 {%0,%1,%2,%3}, [%4];"
                 : "=r"(r[0]), "=r"(r[1]), "=r"(r[2]), "=r"(r[3]) : "r"(addr));
}

__device__ __forceinline__ void mma16816(float* c, const uint32_t* a,
                                         uint32_t b0, uint32_t b1) {
    asm volatile(
        "mma.sync.aligned.m16n8k16.row.col.f32.f16.f16.f32 "
        "{%0,%1,%2,%3}, {%4,%5,%6,%7}, {%8,%9}, {%0,%1,%2,%3};"
        : "+f"(c[0]), "+f"(c[1]), "+f"(c[2]), "+f"(c[3])
        : "r"(a[0]), "r"(a[1]), "r"(a[2]), "r"(a[3]), "r"(b0), "r"(b1));
}

// sparse 2:4 MMA: A 16x32 (compressed 16x16), B 32x8, selector 0
__device__ __forceinline__ void mmasp(float* c, const uint32_t* a,
                                      uint32_t b0, uint32_t b1,
                                      uint32_t b2, uint32_t b3, uint32_t e) {
    asm volatile(
        "mma.sp.sync.aligned.m16n8k32.row.col.f32.f16.f16.f32 "
        "{%0,%1,%2,%3}, {%4,%5,%6,%7}, {%8,%9,%10,%11}, {%0,%1,%2,%3}, %12, 0x0;"
        : "+f"(c[0]), "+f"(c[1]), "+f"(c[2]), "+f"(c[3])
        : "r"(a[0]), "r"(a[1]), "r"(a[2]), "r"(a[3]),
          "r"(b0), "r"(b1), "r"(b2), "r"(b3), "r"(e));
}

// ---------------- prep kernels ----------------
__device__ __forceinline__ void split2(float w, __half& a, __half& b) {
    a = __float2half_rn(w);
    float r1 = w - __half2float(a);
    b = __float2half_rn(r1);
}

// g_Wv2: row index = v*5 + c (argmax-self-contained 80-col tiles)
__global__ void k_prep_wv(const float* __restrict__ W) {
    int i = blockIdx.x * 256 + threadIdx.x;   // over NCV*NH
    int h = i & (NH - 1);
    int row = i >> 8;                         // v*5 + c
    int c = row % NC;
    int v = row / NC;
    __half a, b;
    split2(W[((size_t)(c * NH + h)) * NV + v], a, b);
    g_Wv2[0][i] = a; g_Wv2[1][i] = b;
}

// g_Wh2: [split][h][x = v*5+c]
__global__ void k_prep_wh(const float* __restrict__ W) {
    int x = blockIdx.x * 256 + threadIdx.x;   // 0..2559
    int h = blockIdx.y;
    int v = x / NC;
    int c = x - v * NC;
    __half a, b;
    split2(W[((size_t)(c * NH + h)) * NV + v], a, b);
    size_t o = (size_t)h * NCV + x;
    g_Wh2[0][o] = a; g_Wh2[1][o] = b;
}

// g_idx[b*V+v] = argmax_c v0[b,c,v]  (v0 is exact one-hot)
__global__ void k_extract_idx(const float* __restrict__ v0) {
    int i = blockIdx.x * 256 + threadIdx.x;   // over B*V
    int b = i >> 9;
    int v = i & (NV - 1);
    uint32_t c = 0;
#pragma unroll
    for (int cc = 1; cc < NC; cc++)
        if (v0[((size_t)(b * NC + cc)) * NV + v] > 0.5f) c = cc;
    g_idx[(size_t)b * NV + v] = (uint8_t)c;
}

// Build 2:4 compressed A + metadata from g_idx.  One thread per (b, k32-chunk).
// A k32 chunk can touch v in [vlo, vlo+7] (8 distinct v) -> loc[8].
__global__ void k_build_sparse() {
    int t = blockIdx.x * 256 + threadIdx.x;   // over NB*80
    int kc = t % 80;
    int b  = t / 80;
    int base = kc * 32;
    int vlo = base / NC;
    const uint8_t* idx = g_idx + (size_t)b * NV;
    uint8_t loc[8];
#pragma unroll
    for (int j = 0; j < 8; j++) loc[j] = idx[min(vlo + j, NV - 1)];

    uint32_t meta = 0;
    unsigned short comp[16];
#pragma unroll
    for (int w = 0; w < 8; w++) {
        int x0 = base + w * 4;
        int p0 = -1, p1 = -1;
#pragma unroll
        for (int tt = 0; tt < 4; tt++) {
            int x = x0 + tt;
            int v = x / NC;
            int c = x - v * NC;
            if ((int)loc[v - vlo] == c) { if (p0 < 0) p0 = tt; else p1 = tt; }
        }
        int i0, i1;
        unsigned short v0h, v1h;
        if (p1 >= 0)      { i0 = p0; i1 = p1; v0h = 0x3C00u; v1h = 0x3C00u; }
        else if (p0 >= 0) {
            if (p0 < 3)   { i0 = p0; i1 = 3;  v0h = 0x3C00u; v1h = 0u; }
            else          { i0 = 2;  i1 = 3;  v0h = 0u;      v1h = 0x3C00u; }
        } else            { i0 = 0;  i1 = 1;  v0h = 0u;      v1h = 0u; }
        meta |= (uint32_t)(i0 | (i1 << 2)) << (4 * w);
        comp[2 * w] = v0h; comp[2 * w + 1] = v1h;
    }
    g_meta[(size_t)b * 80 + kc] = meta;
    uint4* dst = (uint4*)(g_Acomp + (size_t)b * 1280 + kc * 16);
    dst[0] = *(uint4*)comp;
    dst[1] = *(uint4*)(comp + 8);
}

// ============ sample_h: sparse GEMM (K'=2560, 2:4) + bernoulli epilogue ============
#define BM 128
#define BN 64
#define ACP 48                         // compressed-A smem row stride (16 fp16 + pad)
#define ROWB 80                        // B smem row stride (32 fp16 + pad)
#define AOFFB 0
#define BOFFB (BM * ACP)               // 6144
#define MOFFB (BOFFB + 2 * BN * ROWB)  // 6144 + 10240 = 16384
#define STGSP (MOFFB + 512)            // 16896
#define SMEMH (3 * STGSP)              // 50688
#define BSPLIT ((size_t)NCV * NH)

__global__ __launch_bounds__(256, 3)
void k_mma_h(const __half* __restrict__ Acomp,
             const uint32_t* __restrict__ Meta,
             const __half* __restrict__ Bsrc,
             uint32_t key0, uint32_t key1,
             const float* __restrict__ cvec,
             float* __restrict__ fout) {
    extern __shared__ char smem[];
    const uint32_t sb = smem_u32(smem);
    const int tid = threadIdx.x;
    const int lane = tid & 31;
    const int wid = tid >> 5;
    const int wm = wid & 3;            // 4 warps along M (32 rows)
    const int wn = wid >> 2;           // 2 warps along N (32 cols)
    const int bn = blockIdx.x * BN;
    const int bm = blockIdx.y * BM;
    const int nk = 80;

    const uint32_t aoff = (uint32_t)((wm * 32 + (lane & 15)) * ACP + (lane >> 4) * 16);
    const uint32_t boff = (uint32_t)((wn * 32 + (lane & 7) + ((lane >> 4) << 3)) * ROWB
                                     + ((lane >> 3) & 1) * 16);
    // metadata: PTX m16n8k32.f16 selector-0 layout.
    // lane 4q+0 word = (row q k0..15) | (row q+8 k0..15)<<16
    // lane 4q+1 word = (row q k16..31)| (row q+8 k16..31)<<16
    const int mq   = lane >> 2;                    // quad index q
    const uint32_t prmsel = (lane & 1) ? 0x7632u : 0x5410u;

    auto issue = [&](int kc) {
        uint32_t s = sb + (kc % 3) * STGSP;
        { int r = tid >> 1, c16 = tid & 1;
          cp16(s + AOFFB + r * ACP + c16 * 16,
               Acomp + (size_t)(bm + r) * 1280 + kc * 16 + c16 * 8); }
#pragma unroll
        for (int i = 0; i < 2; i++) {
            int slot = tid + 256 * i;
            int sp = slot >> 8, rr = (slot >> 2) & 63, s4 = slot & 3;
            cp16(s + BOFFB + sp * (BN * ROWB) + rr * ROWB + s4 * 16,
                 Bsrc + sp * BSPLIT + (size_t)(bn + rr) * NCV + kc * 32 + s4 * 8);
        }
        if (tid < 128)
            cp4(s + MOFFB + tid * 4, Meta + (size_t)(bm + tid) * 80 + kc);
    };

    float acc[2][4][4];
#pragma unroll
    for (int i = 0; i < 2; i++)
#pragma unroll
        for (int j = 0; j < 4; j++)
#pragma unroll
            for (int q = 0; q < 4; q++) acc[i][j][q] = 0.0f;

    issue(0); CP_COMMIT();
    issue(1); CP_COMMIT();

#pragma unroll 1
    for (int kc = 0; kc < nk; kc++) {
        CP_WAIT(1);
        __syncthreads();
        if (kc + 2 < nk) issue(kc + 2);
        CP_COMMIT();

        const uint32_t s = sb + (kc % 3) * STGSP;
        uint32_t a[2][4];
        uint32_t e[2];
#pragma unroll
        for (int mi = 0; mi < 2; mi++) {
            ldmx4(a[mi], s + AOFFB + aoff + (uint32_t)(mi * 16 * ACP));
            // assemble this lane's metadata word from rows (q, q+8) of this m16 tile
            uint32_t m0, m1;
            uint32_t mbase = s + MOFFB + (uint32_t)((wm * 32 + mi * 16 + mq) * 4);
            asm volatile("ld.shared.b32 %0, [%1];" : "=r"(m0) : "r"(mbase));
            asm volatile("ld.shared.b32 %0, [%1];" : "=r"(m1) : "r"(mbase + 32));
            e[mi] = __byte_perm(m0, m1, prmsel);
        }
#pragma unroll
        for (int sp = 0; sp < 2; sp++) {
#pragma unroll
            for (int nh = 0; nh < 2; nh++) {
                uint32_t lo[4], hi[4];
                uint32_t bb = s + BOFFB + sp * (BN * ROWB) + boff
                              + (uint32_t)(nh * 16 * ROWB);
                ldmx4(lo, bb);
                ldmx4(hi, bb + 32);
#pragma unroll
                for (int q = 0; q < 2; q++)
#pragma unroll
                    for (int mi = 0; mi < 2; mi++)
                        mmasp(acc[mi][nh * 2 + q], a[mi],
                              lo[2 * q], lo[2 * q + 1], hi[2 * q], hi[2 * q + 1],
                              e[mi]);
            }
        }
    }

    // epilogue: sigmoid + threefry bernoulli
    const int r4 = lane >> 2;
    const int c2 = (lane & 3) * 2;
#pragma unroll
    for (int mi = 0; mi < 2; mi++) {
#pragma unroll
        for (int ni = 0; ni < 4; ni++) {
            const float* c = acc[mi][ni];
            const int col = bn + wn * 32 + ni * 8 + c2;
            const int row = bm + wm * 32 + mi * 16 + r4;
            const float cv0 = cvec[col], cv1 = cvec[col + 1];
#pragma unroll
            for (int half_ = 0; half_ < 2; half_++) {
                const int rr = row + half_ * 8;
                float x0 = __fadd_rn(c[half_ * 2 + 0], cv0);
                float x1 = __fadd_rn(c[half_ * 2 + 1], cv1);
                float p0 = __fadd_rn(__fmul_rn(0.5f, tanhf(__fmul_rn(0.5f, x0))), 0.5f);
                float p1 = __fadd_rn(__fmul_rn(0.5f, tanhf(__fmul_rn(0.5f, x1))), 0.5f);
                uint32_t gi = (uint32_t)rr * NH + col;
                float u0 = bits_to_unit(rand_bits(key0, key1, gi));
                float u1 = bits_to_unit(rand_bits(key0, key1, gi + 1));
                uint32_t b0 = (u0 < p0) ? 0x3C00u : 0u;
                uint32_t b1 = (u1 < p1) ? 0x3C00u : 0u;
                *(uint32_t*)(g_hb + (size_t)rr * NH + col) = (b1 << 16) | b0;
                if (fout)
                    *(float2*)(fout + (size_t)rr * NH + col) =
                        make_float2(b0 ? 1.0f : 0.0f, b1 ? 1.0f : 0.0f);
            }
        }
    }
}

// ============ sample_v GEMM + fused gumbel-argmax categorical (BN=80) ============
#define ATILE (BM * ROWB)              // 10240 (dense A tile for sample_v)
#define BNV 80
#define BTILEV (BNV * ROWB)            // 6400
#define STGV (ATILE + 2 * BTILEV)      // 23040
#define SMEMV (3 * STGV)               // 69120
#define TS 84
#define BK 32

template<int WRITE_OUT>
__global__ __launch_bounds__(256, 3)
void k_mma_v(const __half* __restrict__ Asrc,   // g_hb, lda = NH
             const __half* __restrict__ Bsrc,   // g_Wv2, rows v*5+c, ldb = NH
             uint32_t key0, uint32_t key1,
             const float* __restrict__ bvec,
             float* __restrict__ vout) {
    extern __shared__ char smem[];
    const uint32_t sb = smem_u32(smem);
    float* tile = (float*)smem;
    const int tid = threadIdx.x;
    const int lane = tid & 31;
    const int wid = tid >> 5;          // 8 warps, each M=16 rows, full N=80
    const int bn = blockIdx.x * BNV;
    const int bm = blockIdx.y * BM;
    const int nk = NH / BK;            // 8

    const int ar0 = tid >> 2;
    const int ac  = (tid & 3) * 16;
    const int ack = (tid & 3) * 8;

    const uint32_t aoff = (uint32_t)((wid * 16 + (lane & 15)) * ROWB + (lane >> 4) * 16);
    const uint32_t boff = (uint32_t)(((lane & 7) + ((lane >> 4) << 3)) * ROWB
                                     + ((lane >> 3) & 1) * 16);

    auto issue = [&](int kc) {
        const int k0 = kc * BK;
        uint32_t s = sb + (kc % 3) * STGV;
        cp16(s + ar0 * ROWB + ac,        Asrc + (size_t)(bm + ar0) * NH + k0 + ack);
        cp16(s + (ar0 + 64) * ROWB + ac, Asrc + (size_t)(bm + ar0 + 64) * NH + k0 + ack);
#pragma unroll
        for (int sp = 0; sp < 2; sp++) {
#pragma unroll
            for (int i = 0; i < 2; i++) {
                int slot = tid + 256 * i;
                if (slot < 4 * BNV) {
                    int row = slot >> 2, col16 = (slot & 3) * 16;
                    cp16(s + ATILE + sp * BTILEV + row * ROWB + col16,
                         Bsrc + sp * BSPLIT + (size_t)(bn + row) * NH + k0 + (slot & 3) * 8);
                }
            }
        }
    };

    float acc[10][4];
#pragma unroll
    for (int j = 0; j < 10; j++)
#pragma unroll
        for (int q = 0; q < 4; q++) acc[j][q] = 0.0f;

    issue(0); CP_COMMIT();
    issue(1); CP_COMMIT();

#pragma unroll 1
    for (int kc = 0; kc < nk; kc++) {
        CP_WAIT(1);
        __syncthreads();
        if (kc + 2 < nk) issue(kc + 2);
        CP_COMMIT();

        const uint32_t sA = sb + (kc % 3) * STGV;
        const uint32_t sB = sA + ATILE;
#pragma unroll
        for (int ks = 0; ks < 2; ks++) {
            uint32_t a[4];
            ldmx4(a, sA + aoff + (uint32_t)(ks * 32));
#pragma unroll
            for (int sp = 0; sp < 2; sp++) {
#pragma unroll
                for (int g = 0; g < 5; g++) {
                    uint32_t b[4];
                    ldmx4(b, sB + sp * BTILEV + boff
                             + (uint32_t)(g * 16 * ROWB + ks * 32));
                    mma16816(acc[g * 2 + 0], a, b[0], b[1]);
                    mma16816(acc[g * 2 + 1], a, b[2], b[3]);
                }
            }
        }
    }

    // ---- epilogue: acc -> smem fp32 tile -> gumbel argmax over c ----
    __syncthreads();
    const int r4 = lane >> 2;
    const int c2 = (lane & 3) * 2;
    const int rw = wid * 16 + r4;
#pragma unroll
    for (int g = 0; g < 10; g++) {
        int col = g * 8 + c2;
        *(float2*)(tile + rw * TS + col)       = make_float2(acc[g][0], acc[g][1]);
        *(float2*)(tile + (rw + 8) * TS + col) = make_float2(acc[g][2], acc[g][3]);
    }
    __syncthreads();

    const int v0g = blockIdx.x * 16;
#pragma unroll 1
    for (int j = 0; j < 8; j++) {
        int idx = tid + 256 * j;
        int r  = idx >> 4;
        int vl = idx & 15;
        int bg = bm + r;
        int vg = v0g + vl;
        float best = 0.0f;
        uint32_t bc = 0;
#pragma unroll
        for (int c = 0; c < NC; c++) {
            float l = __fadd_rn(tile[r * TS + vl * NC + c], bvec[c * NV + vg]);
            uint32_t gi = (((uint32_t)bg * NC + (uint32_t)c) << 9) + (uint32_t)vg;
            float u = bits_to_unit(rand_bits(key0, key1, gi));
            float up = fmaxf(__fadd_rn(u, TINYF), TINYF);
            float gmb = -logf(-logf(up));
            float s = __fadd_rn(gmb, l);
            if (c == 0 || s > best) { best = s; bc = (uint32_t)c; }
        }
        g_idx[(size_t)bg * NV + vg] = (uint8_t)bc;
        if (WRITE_OUT) {
#pragma unroll
            for (int c = 0; c < NC; c++)
                vout[(size_t)bg * NCV + c * NV + vg] = (c == (int)bc) ? 1.0f : 0.0f;
        }
    }
}

// ---------------- launcher ----------------
extern "C" void kernel_launch(void* const* d_in, const int* in_sizes, int n_in,
                              void* d_out, int out_size) {
    const float* v0 = (const float*)d_in[0];
    const float* W  = (const float*)d_in[1];
    const float* bb = (const float*)d_in[2];
    const float* cc = (const float*)d_in[3];
    (void)in_sizes; (void)n_in; (void)out_size;

    float* out    = (float*)d_out;
    float* out_v  = out;
    float* out_h  = out + (size_t)NBCV;
    float* out_h0 = out_h + (size_t)NBH;

    uint32_t keys[5][2];
    for (uint32_t i = 0; i < 5; i++)
        threefry(0u, 42u, 0u, i, keys[i][0], keys[i][1]);

    cudaFuncSetAttribute(k_mma_h,    cudaFuncAttributeMaxDynamicSharedMemorySize, SMEMH);
    cudaFuncSetAttribute(k_mma_v<0>, cudaFuncAttributeMaxDynamicSharedMemorySize, SMEMV);
    cudaFuncSetAttribute(k_mma_v<1>, cudaFuncAttributeMaxDynamicSharedMemorySize, SMEMV);

    void *pHB, *pWv, *pWh, *pAc, *pMe;
    cudaGetSymbolAddress(&pHB, g_hb);
    cudaGetSymbolAddress(&pWv, g_Wv2);
    cudaGetSymbolAddress(&pWh, g_Wh2);
    cudaGetSymbolAddress(&pAc, g_Acomp);
    cudaGetSymbolAddress(&pMe, g_meta);
    const __half* HB    = (const __half*)pHB;
    const __half* Wv2   = (const __half*)pWv;
    const __half* Wh2   = (const __half*)pWh;
    const __half* Acomp = (const __half*)pAc;
    const uint32_t* Meta = (const uint32_t*)pMe;

    dim3 gh(NH / BN, NB / BM);      // (4, 128)
    dim3 gv(NCV / BNV, NB / BM);    // (32, 128)
    const int nbs = NB * 80 / 256;  // build_sparse grid

    k_prep_wv<<<NCV * NH / 256, 256>>>(W);
    k_prep_wh<<<dim3(NCV / 256, NH), 256>>>(W);
    k_extract_idx<<<NB * NV / 256, 256>>>(v0);
    k_build_sparse<<<nbs, 256>>>();

    // h = sample_h(keys[0], v0) -> out_h0
    k_mma_h<<<gh, 256, SMEMH>>>(Acomp, Meta, Wh2, keys[0][0], keys[0][1], cc, out_h0);
    // iter 0
    k_mma_v<0><<<gv, 256, SMEMV>>>(HB, Wv2, keys[1][0], keys[1][1], bb, nullptr);
    k_build_sparse<<<nbs, 256>>>();
    k_mma_h<<<gh, 256, SMEMH>>>(Acomp, Meta, Wh2, keys[2][0], keys[2][1], cc, nullptr);
    // iter 1
    k_mma_v<1><<<gv, 256, SMEMV>>>(HB, Wv2, keys[3][0], keys[3][1], bb, out_v);
    k_build_sparse<<<nbs, 256>>>();
    k_mma_h<<<gh, 256, SMEMH>>>(Acomp, Meta, Wh2, keys[4][0], keys[4][1], cc, out_h);
}

// round 13
// speedup vs baseline: 1.3962x; 1.3962x over previous
#include <cuda_runtime.h>
#include <cuda_fp16.h>
#include <cstdint>
#include <math.h>

// Problem constants
#define NB 16384
#define NC 5
#define NH 256
#define NV 512
#define NCV 2560
#define NBH 4194304
#define NBCV 41943040u
#define TINYF 1.17549435082228751e-38f

// int8 W split scales: ratio 254 per stage (avoids clamp overflow at rint ties)
#define WS1 4.8828125e-4f               // 2^-11
#define IWS1 2048.0f
#define WS2 (1.0f / 520192.0f)          // WS1/254
#define IWS2 520192.0f
#define WS3 (1.0f / 132128768.0f)       // WS2/254
#define IWS3 132128768.0f

// ---------------- scratch (static device globals) ----------------
__device__ __half  g_hb[(size_t)NB * NH];      // h fp16 (A for sample_v, K=256)
__device__ int8_t  g_A8[(size_t)NB * NCV];     // one-hot v s8, x = v*5+c (A for sample_h)
__device__ int8_t  g_Wh8[3][NH * NCV];         // [split][h*2560 + x]  (B for sample_h, s8)
__device__ __half  g_Wv2[2][NCV * NH];         // [split][v*5+c][h]    (B for sample_v, fp16)

// ---------------- threefry2x32 (bit-exact with JAX, partitionable) ----------------
__host__ __device__ __forceinline__ uint32_t rotl32(uint32_t x, int r) {
#ifdef __CUDA_ARCH__
    return __funnelshift_l(x, x, r);
#else
    return (x << r) | (x >> (32 - r));
#endif
}

__host__ __device__ inline void threefry(uint32_t k0, uint32_t k1,
                                         uint32_t x0, uint32_t x1,
                                         uint32_t& o0, uint32_t& o1) {
    uint32_t k2 = k0 ^ k1 ^ 0x1BD11BDAu;
#define TFR(r) { x0 += x1; x1 = rotl32(x1, (r)); x1 ^= x0; }
    x0 += k0; x1 += k1;
    TFR(13) TFR(15) TFR(26) TFR(6)   x0 += k1; x1 += k2 + 1u;
    TFR(17) TFR(29) TFR(16) TFR(24)  x0 += k2; x1 += k0 + 2u;
    TFR(13) TFR(15) TFR(26) TFR(6)   x0 += k0; x1 += k1 + 3u;
    TFR(17) TFR(29) TFR(16) TFR(24)  x0 += k1; x1 += k2 + 4u;
    TFR(13) TFR(15) TFR(26) TFR(6)   x0 += k2; x1 += k0 + 5u;
#undef TFR
    o0 = x0; o1 = x1;
}

__device__ __forceinline__ uint32_t rand_bits(uint32_t k0, uint32_t k1, uint32_t i) {
    uint32_t a, b;
    threefry(k0, k1, 0u, i, a, b);
    return a ^ b;
}

__device__ __forceinline__ float bits_to_unit(uint32_t bits) {
    return __fadd_rn(__uint_as_float((bits >> 9) | 0x3f800000u), -1.0f);
}

// ---------------- small helpers ----------------
__device__ __forceinline__ uint32_t smem_u32(const void* p) {
    uint32_t a;
    asm("{ .reg .u64 t; cvta.to.shared.u64 t, %1; cvt.u32.u64 %0, t; }" : "=r"(a) : "l"(p));
    return a;
}

__device__ __forceinline__ void cp16(uint32_t s, const void* g) {
    asm volatile("cp.async.cg.shared.global [%0], [%1], 16;" :: "r"(s), "l"(g));
}
#define CP_COMMIT() asm volatile("cp.async.commit_group;" ::: "memory")
#define CP_WAIT(n)  asm volatile("cp.async.wait_group %0;" :: "n"(n) : "memory")

__device__ __forceinline__ void ldmx4(uint32_t* r, uint32_t addr) {
    asm volatile("ldmatrix.sync.aligned.m8n8.x4.shared.b16 {%0,%1,%2,%3}, [%4];"
                 : "=r"(r[0]), "=r"(r[1]), "=r"(r[2]), "=r"(r[3]) : "r"(addr));
}

__device__ __forceinline__ void mma16816(float* c, const uint32_t* a,
                                         uint32_t b0, uint32_t b1) {
    asm volatile(
        "mma.sync.aligned.m16n8k16.row.col.f32.f16.f16.f32 "
        "{%0,%1,%2,%3}, {%4,%5,%6,%7}, {%8,%9}, {%0,%1,%2,%3};"
        : "+f"(c[0]), "+f"(c[1]), "+f"(c[2]), "+f"(c[3])
        : "r"(a[0]), "r"(a[1]), "r"(a[2]), "r"(a[3]), "r"(b0), "r"(b1));
}

// int8 MMA: A 16x32 s8, B 32x8 s8, s32 accum
__device__ __forceinline__ void imma16832(int* c, const uint32_t* a,
                                          uint32_t b0, uint32_t b1) {
    asm volatile(
        "mma.sync.aligned.m16n8k32.row.col.s32.s8.s8.s32 "
        "{%0,%1,%2,%3}, {%4,%5,%6,%7}, {%8,%9}, {%0,%1,%2,%3};"
        : "+r"(c[0]), "+r"(c[1]), "+r"(c[2]), "+r"(c[3])
        : "r"(a[0]), "r"(a[1]), "r"(a[2]), "r"(a[3]), "r"(b0), "r"(b1));
}

// ---------------- prep kernels ----------------
__device__ __forceinline__ void split2h(float w, __half& a, __half& b) {
    a = __float2half_rn(w);
    float r1 = w - __half2float(a);
    b = __float2half_rn(r1);
}

// g_Wv2: row index = v*5 + c (argmax-self-contained 80-col tiles), fp16 2-split
__global__ void k_prep_wv(const float* __restrict__ W) {
    int i = blockIdx.x * 256 + threadIdx.x;   // over NCV*NH
    int h = i & (NH - 1);
    int row = i >> 8;                         // v*5 + c
    int c = row % NC;
    int v = row / NC;
    __half a, b;
    split2h(W[((size_t)(c * NH + h)) * NV + v], a, b);
    g_Wv2[0][i] = a; g_Wv2[1][i] = b;
}

// g_Wh8: [split][h][x = v*5+c], int8 3-split with ratio-254 stages
__global__ void k_prep_wh(const float* __restrict__ W) {
    int x = blockIdx.x * 256 + threadIdx.x;   // 0..2559
    int h = blockIdx.y;
    int v = x / NC;
    int c = x - v * NC;
    float w = W[((size_t)(c * NH + h)) * NV + v];
    float w1 = rintf(w * IWS1);
    w1 = fminf(fmaxf(w1, -127.0f), 127.0f);
    float r1 = w - w1 * WS1;                  // WS1 pow2 -> exact
    float w2 = rintf(r1 * IWS2);
    w2 = fminf(fmaxf(w2, -127.0f), 127.0f);
    float r2 = r1 - w2 * WS2;
    float w3 = rintf(r2 * IWS3);
    w3 = fminf(fmaxf(w3, -127.0f), 127.0f);
    size_t o = (size_t)h * NCV + x;
    g_Wh8[0][o] = (int8_t)(int)w1;
    g_Wh8[1][o] = (int8_t)(int)w2;
    g_Wh8[2][o] = (int8_t)(int)w3;
}

// A8[b][v*5+c] = onehot from v0 (exact one-hot fp32)
__global__ void k_extract_a8(const float* __restrict__ v0) {
    int i = blockIdx.x * 256 + threadIdx.x;   // over B*V
    int b = i >> 9;
    int v = i & (NV - 1);
    int c = 0;
#pragma unroll
    for (int cc = 1; cc < NC; cc++)
        if (v0[((size_t)(b * NC + cc)) * NV + v] > 0.5f) c = cc;
    int8_t* dst = g_A8 + (size_t)b * NCV + v * NC;
#pragma unroll
    for (int cc = 0; cc < NC; cc++) dst[cc] = (cc == c) ? 1 : 0;
}

// ============ sample_h: int8 3-split GEMM (K=2560) + bernoulli epilogue ============
// CTA 128(M=b) x 32(N=h); 8 warps of m16 x n32; BK=32 bytes; split-major K loop (240 chunks).
#define BMH 128
#define BNH 32
#define ARW 48                          // smem row stride bytes (32B data + 16B pad)
#define ASZ (BMH * ARW)                 // 6144
#define BSZ (BNH * ARW)                 // 1536
#define STGH (ASZ + BSZ)                // 7680
#define NSTH 4
#define SMEMH (NSTH * STGH)             // 30720
#define WSPLIT ((size_t)NH * NCV)

__global__ __launch_bounds__(256, 3)
void k_mma_h(const int8_t* __restrict__ A8,
             const int8_t* __restrict__ Bsrc,
             uint32_t key0, uint32_t key1,
             const float* __restrict__ cvec,
             float* __restrict__ fout) {
    extern __shared__ char smem[];
    const uint32_t sb = smem_u32(smem);
    const int tid = threadIdx.x;
    const int lane = tid & 31;
    const int wid = tid >> 5;              // 8 warps, m16 each, full n32
    const int bn = blockIdx.x * BNH;
    const int bm = blockIdx.y * BMH;

    const uint32_t aoff = (uint32_t)((wid * 16 + (lane & 15)) * ARW + (lane >> 4) * 16);
    const uint32_t boff = (uint32_t)(((lane & 7) + ((lane >> 4) << 3)) * ARW
                                     + ((lane >> 3) & 1) * 16);

    auto issue = [&](int t) {
        int sp = (t >= 160) ? 2 : (t >= 80) ? 1 : 0;
        int kc = t - sp * 80;
        uint32_t s = sb + (t & 3) * STGH;
        { int r = tid >> 1, c16 = (tid & 1) * 16;
          cp16(s + r * ARW + c16, A8 + (size_t)(bm + r) * NCV + kc * 32 + c16); }
        if (tid < 64) {
            int rr = tid >> 1, c16 = (tid & 1) * 16;
            cp16(s + ASZ + rr * ARW + c16,
                 Bsrc + sp * WSPLIT + (size_t)(bn + rr) * NCV + kc * 32 + c16);
        }
    };

    int   acc[4][4];
    float accf[4][4];
#pragma unroll
    for (int j = 0; j < 4; j++)
#pragma unroll
        for (int q = 0; q < 4; q++) { acc[j][q] = 0; accf[j][q] = 0.0f; }

    issue(0); CP_COMMIT();
    issue(1); CP_COMMIT();
    issue(2); CP_COMMIT();

#pragma unroll 1
    for (int t = 0; t < 240; t++) {
        CP_WAIT(2);
        __syncthreads();
        if (t + 3 < 240) issue(t + 3);
        CP_COMMIT();

        const uint32_t s = sb + (t & 3) * STGH;
        uint32_t a[4];
        ldmx4(a, s + aoff);
#pragma unroll
        for (int nh = 0; nh < 2; nh++) {
            uint32_t b[4];
            ldmx4(b, s + ASZ + boff + (uint32_t)(nh * 16 * ARW));
            imma16832(acc[nh * 2 + 0], a, b[0], b[1]);
            imma16832(acc[nh * 2 + 1], a, b[2], b[3]);
        }
        if (t == 79 || t == 159 || t == 239) {
            float sc = (t == 79) ? WS1 : (t == 159) ? WS2 : WS3;
#pragma unroll
            for (int j = 0; j < 4; j++)
#pragma unroll
                for (int q = 0; q < 4; q++) {
                    accf[j][q] = fmaf((float)acc[j][q], sc, accf[j][q]);
                    acc[j][q] = 0;
                }
        }
    }

    // epilogue: sigmoid + threefry bernoulli
    const int r4 = lane >> 2;
    const int c2 = (lane & 3) * 2;
#pragma unroll
    for (int ni = 0; ni < 4; ni++) {
        const float* c = accf[ni];
        const int col = bn + ni * 8 + c2;
        const int row = bm + wid * 16 + r4;
        const float cv0 = cvec[col], cv1 = cvec[col + 1];
#pragma unroll
        for (int half_ = 0; half_ < 2; half_++) {
            const int rr = row + half_ * 8;
            float x0 = __fadd_rn(c[half_ * 2 + 0], cv0);
            float x1 = __fadd_rn(c[half_ * 2 + 1], cv1);
            float p0 = __fadd_rn(__fmul_rn(0.5f, tanhf(__fmul_rn(0.5f, x0))), 0.5f);
            float p1 = __fadd_rn(__fmul_rn(0.5f, tanhf(__fmul_rn(0.5f, x1))), 0.5f);
            uint32_t gi = (uint32_t)rr * NH + col;
            float u0 = bits_to_unit(rand_bits(key0, key1, gi));
            float u1 = bits_to_unit(rand_bits(key0, key1, gi + 1));
            uint32_t b0 = (u0 < p0) ? 0x3C00u : 0u;   // fp16 1.0
            uint32_t b1 = (u1 < p1) ? 0x3C00u : 0u;
            *(uint32_t*)(g_hb + (size_t)rr * NH + col) = (b1 << 16) | b0;
            if (fout)
                *(float2*)(fout + (size_t)rr * NH + col) =
                    make_float2(b0 ? 1.0f : 0.0f, b1 ? 1.0f : 0.0f);
        }
    }
}

// ============ sample_v fp16 GEMM + fused gumbel-argmax categorical (BN=80) ============
#define BM 128
#define BK 32
#define ROWB 80
#define ATILE (BM * ROWB)              // 10240
#define BNV 80
#define BTILEV (BNV * ROWB)            // 6400
#define STGV (ATILE + 2 * BTILEV)      // 23040
#define SMEMV (3 * STGV)               // 69120
#define TS 84
#define BSPLITV ((size_t)NCV * NH)

template<int WRITE_OUT>
__global__ __launch_bounds__(256, 3)
void k_mma_v(const __half* __restrict__ Asrc,   // g_hb, lda = NH
             const __half* __restrict__ Bsrc,   // g_Wv2, rows v*5+c, ldb = NH
             uint32_t key0, uint32_t key1,
             const float* __restrict__ bvec,
             float* __restrict__ vout) {
    extern __shared__ char smem[];
    const uint32_t sb = smem_u32(smem);
    float* tile = (float*)smem;
    const int tid = threadIdx.x;
    const int lane = tid & 31;
    const int wid = tid >> 5;          // 8 warps, each M=16 rows, full N=80
    const int bn = blockIdx.x * BNV;
    const int bm = blockIdx.y * BM;
    const int nk = NH / BK;            // 8

    const int ar0 = tid >> 2;
    const int ac  = (tid & 3) * 16;
    const int ack = (tid & 3) * 8;

    const uint32_t aoff = (uint32_t)((wid * 16 + (lane & 15)) * ROWB + (lane >> 4) * 16);
    const uint32_t boff = (uint32_t)(((lane & 7) + ((lane >> 4) << 3)) * ROWB
                                     + ((lane >> 3) & 1) * 16);

    auto issue = [&](int kc) {
        const int k0 = kc * BK;
        uint32_t s = sb + (kc % 3) * STGV;
        cp16(s + ar0 * ROWB + ac,        Asrc + (size_t)(bm + ar0) * NH + k0 + ack);
        cp16(s + (ar0 + 64) * ROWB + ac, Asrc + (size_t)(bm + ar0 + 64) * NH + k0 + ack);
#pragma unroll
        for (int sp = 0; sp < 2; sp++) {
#pragma unroll
            for (int i = 0; i < 2; i++) {
                int slot = tid + 256 * i;
                if (slot < 4 * BNV) {
                    int row = slot >> 2, col16 = (slot & 3) * 16;
                    cp16(s + ATILE + sp * BTILEV + row * ROWB + col16,
                         Bsrc + sp * BSPLITV + (size_t)(bn + row) * NH + k0 + (slot & 3) * 8);
                }
            }
        }
    };

    float acc[10][4];
#pragma unroll
    for (int j = 0; j < 10; j++)
#pragma unroll
        for (int q = 0; q < 4; q++) acc[j][q] = 0.0f;

    issue(0); CP_COMMIT();
    issue(1); CP_COMMIT();

#pragma unroll 1
    for (int kc = 0; kc < nk; kc++) {
        CP_WAIT(1);
        __syncthreads();
        if (kc + 2 < nk) issue(kc + 2);
        CP_COMMIT();

        const uint32_t sA = sb + (kc % 3) * STGV;
        const uint32_t sB = sA + ATILE;
#pragma unroll
        for (int ks = 0; ks < 2; ks++) {
            uint32_t a[4];
            ldmx4(a, sA + aoff + (uint32_t)(ks * 32));
#pragma unroll
            for (int sp = 0; sp < 2; sp++) {
#pragma unroll
                for (int g = 0; g < 5; g++) {
                    uint32_t b[4];
                    ldmx4(b, sB + sp * BTILEV + boff
                             + (uint32_t)(g * 16 * ROWB + ks * 32));
                    mma16816(acc[g * 2 + 0], a, b[0], b[1]);
                    mma16816(acc[g * 2 + 1], a, b[2], b[3]);
                }
            }
        }
    }

    // ---- epilogue: acc -> smem fp32 tile -> gumbel argmax over c ----
    __syncthreads();
    const int r4 = lane >> 2;
    const int c2 = (lane & 3) * 2;
    const int rw = wid * 16 + r4;
#pragma unroll
    for (int g = 0; g < 10; g++) {
        int col = g * 8 + c2;
        *(float2*)(tile + rw * TS + col)       = make_float2(acc[g][0], acc[g][1]);
        *(float2*)(tile + (rw + 8) * TS + col) = make_float2(acc[g][2], acc[g][3]);
    }
    __syncthreads();

    const int v0g = blockIdx.x * 16;
#pragma unroll 1
    for (int j = 0; j < 8; j++) {
        int idx = tid + 256 * j;
        int r  = idx >> 4;
        int vl = idx & 15;
        int bg = bm + r;
        int vg = v0g + vl;
        float best = 0.0f;
        uint32_t bc = 0;
#pragma unroll
        for (int c = 0; c < NC; c++) {
            float l = __fadd_rn(tile[r * TS + vl * NC + c], bvec[c * NV + vg]);
            uint32_t gi = (((uint32_t)bg * NC + (uint32_t)c) << 9) + (uint32_t)vg;
            float u = bits_to_unit(rand_bits(key0, key1, gi));
            float up = fmaxf(__fadd_rn(u, TINYF), TINYF);
            float gmb = -logf(-logf(up));
            float s = __fadd_rn(gmb, l);
            if (c == 0 || s > best) { best = s; bc = (uint32_t)c; }
        }
        int8_t* dst = g_A8 + (size_t)bg * NCV + vg * NC;
#pragma unroll
        for (int c = 0; c < NC; c++) dst[c] = (c == (int)bc) ? 1 : 0;
        if (WRITE_OUT) {
#pragma unroll
            for (int c = 0; c < NC; c++)
                vout[(size_t)bg * NCV + c * NV + vg] = (c == (int)bc) ? 1.0f : 0.0f;
        }
    }
}

// ---------------- launcher ----------------
extern "C" void kernel_launch(void* const* d_in, const int* in_sizes, int n_in,
                              void* d_out, int out_size) {
    const float* v0 = (const float*)d_in[0];
    const float* W  = (const float*)d_in[1];
    const float* bb = (const float*)d_in[2];
    const float* cc = (const float*)d_in[3];
    (void)in_sizes; (void)n_in; (void)out_size;

    float* out    = (float*)d_out;
    float* out_v  = out;
    float* out_h  = out + (size_t)NBCV;
    float* out_h0 = out_h + (size_t)NBH;

    uint32_t keys[5][2];
    for (uint32_t i = 0; i < 5; i++)
        threefry(0u, 42u, 0u, i, keys[i][0], keys[i][1]);

    cudaFuncSetAttribute(k_mma_h,    cudaFuncAttributeMaxDynamicSharedMemorySize, SMEMH);
    cudaFuncSetAttribute(k_mma_v<0>, cudaFuncAttributeMaxDynamicSharedMemorySize, SMEMV);
    cudaFuncSetAttribute(k_mma_v<1>, cudaFuncAttributeMaxDynamicSharedMemorySize, SMEMV);

    void *pHB, *pWv, *pWh, *pA8;
    cudaGetSymbolAddress(&pHB, g_hb);
    cudaGetSymbolAddress(&pWv, g_Wv2);
    cudaGetSymbolAddress(&pWh, g_Wh8);
    cudaGetSymbolAddress(&pA8, g_A8);
    const __half*  HB  = (const __half*)pHB;
    const __half*  Wv2 = (const __half*)pWv;
    const int8_t*  Wh8 = (const int8_t*)pWh;
    const int8_t*  A8  = (const int8_t*)pA8;

    dim3 gh(NH / BNH, NB / BMH);    // (8, 128)
    dim3 gv(NCV / BNV, NB / BM);    // (32, 128)

    k_prep_wv<<<NCV * NH / 256, 256>>>(W);
    k_prep_wh<<<dim3(NCV / 256, NH), 256>>>(W);
    k_extract_a8<<<NB * NV / 256, 256>>>(v0);

    // h = sample_h(keys[0], v0) -> out_h0
    k_mma_h<<<gh, 256, SMEMH>>>(A8, Wh8, keys[0][0], keys[0][1], cc, out_h0);
    // iter 0
    k_mma_v<0><<<gv, 256, SMEMV>>>(HB, Wv2, keys[1][0], keys[1][1], bb, nullptr);
    k_mma_h<<<gh, 256, SMEMH>>>(A8, Wh8, keys[2][0], keys[2][1], cc, nullptr);
    // iter 1
    k_mma_v<1><<<gv, 256, SMEMV>>>(HB, Wv2, keys[3][0], keys[3][1], bb, out_v);
    k_mma_h<<<gh, 256, SMEMH>>>(A8, Wh8, keys[4][0], keys[4][1], cc, out_h);
}

// round 14
// speedup vs baseline: 2.5329x; 1.8141x over previous
#include <cuda_runtime.h>
#include <cuda_fp16.h>
#include <cstdint>
#include <math.h>

// Problem constants
#define NB 16384
#define NC 5
#define NH 256
#define NV 512
#define NCV 2560
#define NBH 4194304
#define NBCV 41943040u
#define TINYF 1.17549435082228751e-38f

#define SC2UP 2048.0f                  // split-2 scale (2^11)
#define SC2DN 4.8828125e-4f            // 2^-11

// ---------------- scratch (static device globals) ----------------
__device__ __half g_A[(size_t)NB * NCV];     // one-hot v fp16 (A for sample_h, K=2560), cv = c*512+v
__device__ __half g_hb[(size_t)NB * NH];     // h fp16 (A for sample_v, K=256)
__device__ __half g_Wv2[2][NCV * NH];        // [split][v*5+c][h]  (B for sample_v; split2 unscaled)
__device__ __half g_Wh2[2][NH * NCV];        // [split][h][c*512+v] (B for sample_h; split2 SCALED 2^11)

// ---------------- threefry2x32 (bit-exact with JAX, partitionable) ----------------
__host__ __device__ __forceinline__ uint32_t rotl32(uint32_t x, int r) {
#ifdef __CUDA_ARCH__
    return __funnelshift_l(x, x, r);
#else
    return (x << r) | (x >> (32 - r));
#endif
}

__host__ __device__ inline void threefry(uint32_t k0, uint32_t k1,
                                         uint32_t x0, uint32_t x1,
                                         uint32_t& o0, uint32_t& o1) {
    uint32_t k2 = k0 ^ k1 ^ 0x1BD11BDAu;
#define TFR(r) { x0 += x1; x1 = rotl32(x1, (r)); x1 ^= x0; }
    x0 += k0; x1 += k1;
    TFR(13) TFR(15) TFR(26) TFR(6)   x0 += k1; x1 += k2 + 1u;
    TFR(17) TFR(29) TFR(16) TFR(24)  x0 += k2; x1 += k0 + 2u;
    TFR(13) TFR(15) TFR(26) TFR(6)   x0 += k0; x1 += k1 + 3u;
    TFR(17) TFR(29) TFR(16) TFR(24)  x0 += k1; x1 += k2 + 4u;
    TFR(13) TFR(15) TFR(26) TFR(6)   x0 += k2; x1 += k0 + 5u;
#undef TFR
    o0 = x0; o1 = x1;
}

__device__ __forceinline__ uint32_t rand_bits(uint32_t k0, uint32_t k1, uint32_t i) {
    uint32_t a, b;
    threefry(k0, k1, 0u, i, a, b);
    return a ^ b;
}

__device__ __forceinline__ float bits_to_unit(uint32_t bits) {
    return __fadd_rn(__uint_as_float((bits >> 9) | 0x3f800000u), -1.0f);
}

// ---------------- small helpers ----------------
__device__ __forceinline__ uint32_t smem_u32(const void* p) {
    uint32_t a;
    asm("{ .reg .u64 t; cvta.to.shared.u64 t, %1; cvt.u32.u64 %0, t; }" : "=r"(a) : "l"(p));
    return a;
}

__device__ __forceinline__ void cp16(uint32_t s, const void* g) {
    asm volatile("cp.async.cg.shared.global [%0], [%1], 16;" :: "r"(s), "l"(g));
}
#define CP_COMMIT() asm volatile("cp.async.commit_group;" ::: "memory")
#define CP_WAIT(n)  asm volatile("cp.async.wait_group %0;" :: "n"(n) : "memory")

__device__ __forceinline__ void ldmx4(uint32_t* r, uint32_t addr) {
    asm volatile("ldmatrix.sync.aligned.m8n8.x4.shared.b16 {%0,%1,%2,%3}, [%4];"
                 : "=r"(r[0]), "=r"(r[1]), "=r"(r[2]), "=r"(r[3]) : "r"(addr));
}

__device__ __forceinline__ void mma16816(float* c, const uint32_t* a,
                                         uint32_t b0, uint32_t b1) {
    asm volatile(
        "mma.sync.aligned.m16n8k16.row.col.f32.f16.f16.f32 "
        "{%0,%1,%2,%3}, {%4,%5,%6,%7}, {%8,%9}, {%0,%1,%2,%3};"
        : "+f"(c[0]), "+f"(c[1]), "+f"(c[2]), "+f"(c[3])
        : "r"(a[0]), "r"(a[1]), "r"(a[2]), "r"(a[3]), "r"(b0), "r"(b1));
}

// f16-accumulate MMA (full-rate): D/C are 2x f16x2 regs: d0={c0,c1}, d1={c2,c3}
__device__ __forceinline__ void mma16816h(uint32_t* c, const uint32_t* a,
                                          uint32_t b0, uint32_t b1) {
    asm volatile(
        "mma.sync.aligned.m16n8k16.row.col.f16.f16.f16.f16 "
        "{%0,%1}, {%2,%3,%4,%5}, {%6,%7}, {%0,%1};"
        : "+r"(c[0]), "+r"(c[1])
        : "r"(a[0]), "r"(a[1]), "r"(a[2]), "r"(a[3]), "r"(b0), "r"(b1));
}

// ---------------- prep kernels ----------------
// g_Wv2: row index = v*5 + c, fp16 2-split (split2 unscaled; f32-accum path)
__global__ void k_prep_wv(const float* __restrict__ W) {
    int i = blockIdx.x * 256 + threadIdx.x;   // over NCV*NH
    int h = i & (NH - 1);
    int row = i >> 8;                         // v*5 + c
    int c = row % NC;
    int v = row / NC;
    float w = W[((size_t)(c * NH + h)) * NV + v];
    __half a = __float2half_rn(w);
    float r1 = w - __half2float(a);
    g_Wv2[0][i] = a;
    g_Wv2[1][i] = __float2half_rn(r1);
}

// g_Wh2: [split][h][cv = c*512+v]; split2 scaled by 2^11 (f16-accum path)
__global__ void k_prep_wh(const float* __restrict__ W) {
    int cv = blockIdx.x * 256 + threadIdx.x;  // 0..2559  (c*512+v)
    int h  = blockIdx.y;
    int v = cv & (NV - 1);
    int c = cv >> 9;
    float w = W[((size_t)(c * NH + h)) * NV + v];
    __half a = __float2half_rn(w);
    float r1 = w - __half2float(a);
    size_t o = (size_t)h * NCV + cv;
    g_Wh2[0][o] = a;
    g_Wh2[1][o] = __float2half_rn(r1 * SC2UP);
}

// g_A = fp16(v0)  (v0 is exact one-hot; layout identical, k = c*512+v)
__global__ void k_cast_A0(const float* __restrict__ v0) {
    size_t i = ((size_t)blockIdx.x * 256 + threadIdx.x) * 4;
    float4 f = *(const float4*)(v0 + i);
    __half o[4] = {__float2half_rn(f.x), __float2half_rn(f.y),
                   __float2half_rn(f.z), __float2half_rn(f.w)};
    *(uint2*)(g_A + i) = *(uint2*)o;
}

// ============ sample_h: 2-split GEMM, split2 in f16-accum (K=2560) ============
// CTA 128(M) x 32(N); 8 warps, each m16 x n32; BK=32; 3-stage cp.async.
#define BMH 128
#define BNH 32
#define ARWH 80                        // 64B data + 16B pad per k32-chunk row
#define ASZH (BMH * ARWH)              // 10240
#define BSZH (BNH * ARWH)              // 2560 per split
#define STGH (ASZH + 2 * BSZH)         // 15360
#define SMEMH (3 * STGH)               // 46080
#define WSPLITH ((size_t)NH * NCV)

__global__ __launch_bounds__(256, 3)
void k_mma_h(const __half* __restrict__ Asrc,
             const __half* __restrict__ Bsrc,
             uint32_t key0, uint32_t key1,
             const float* __restrict__ cvec,
             float* __restrict__ fout) {
    extern __shared__ char smem[];
    const uint32_t sb = smem_u32(smem);
    const int tid = threadIdx.x;
    const int lane = tid & 31;
    const int wid = tid >> 5;              // 8 warps, m16 each, full n32
    const int bn = blockIdx.x * BNH;
    const int bm = blockIdx.y * BMH;
    const int nk = NCV / 32;               // 80

    const uint32_t aoff = (uint32_t)((wid * 16 + (lane & 15)) * ARWH + (lane >> 4) * 16);
    const uint32_t boff = (uint32_t)(((lane & 7) + ((lane >> 4) << 3)) * ARWH
                                     + ((lane >> 3) & 1) * 16);

    auto issue = [&](int kc) {
        uint32_t s = sb + (kc % 3) * STGH;
        // A: 128 rows x 64B -> 512 cp16 (2 per thread)
#pragma unroll
        for (int i = 0; i < 2; i++) {
            int slot = tid + 256 * i;
            int r = slot >> 2, c16 = (slot & 3) * 16;
            cp16(s + r * ARWH + c16,
                 Asrc + (size_t)(bm + r) * NCV + kc * 32 + (slot & 3) * 8);
        }
        // B: 2 splits x 32 rows x 64B -> 256 cp16 (1 per thread)
        {
            int sp = tid >> 7, rr = (tid >> 2) & 31, c16 = (tid & 3) * 16;
            cp16(s + ASZH + sp * BSZH + rr * ARWH + c16,
                 Bsrc + sp * WSPLITH + (size_t)(bn + rr) * NCV + kc * 32 + (tid & 3) * 8);
        }
    };

    float    accf[4][4];
    uint32_t acc2[4][2];
#pragma unroll
    for (int j = 0; j < 4; j++) {
#pragma unroll
        for (int q = 0; q < 4; q++) accf[j][q] = 0.0f;
        acc2[j][0] = 0u; acc2[j][1] = 0u;
    }

    issue(0); CP_COMMIT();
    issue(1); CP_COMMIT();

#pragma unroll 1
    for (int t = 0; t < nk; t++) {
        CP_WAIT(1);
        __syncthreads();
        if (t + 2 < nk) issue(t + 2);
        CP_COMMIT();

        const uint32_t s = sb + (t % 3) * STGH;
#pragma unroll
        for (int ks = 0; ks < 2; ks++) {
            uint32_t a[4];
            ldmx4(a, s + aoff + (uint32_t)(ks * 32));
            // split 1 (f32 accum)
#pragma unroll
            for (int nh = 0; nh < 2; nh++) {
                uint32_t b[4];
                ldmx4(b, s + ASZH + boff + (uint32_t)(nh * 16 * ARWH + ks * 32));
                mma16816(accf[nh * 2 + 0], a, b[0], b[1]);
                mma16816(accf[nh * 2 + 1], a, b[2], b[3]);
            }
            // split 2 (scaled, f16 accum)
#pragma unroll
            for (int nh = 0; nh < 2; nh++) {
                uint32_t b[4];
                ldmx4(b, s + ASZH + BSZH + boff + (uint32_t)(nh * 16 * ARWH + ks * 32));
                mma16816h(acc2[nh * 2 + 0], a, b[0], b[1]);
                mma16816h(acc2[nh * 2 + 1], a, b[2], b[3]);
            }
        }
        // promote f16 accumulators every 16 chunks (t = 15,31,47,63,79)
        if ((t & 15) == 15) {
#pragma unroll
            for (int j = 0; j < 4; j++) {
                __half2 d0 = *(__half2*)&acc2[j][0];
                __half2 d1 = *(__half2*)&acc2[j][1];
                accf[j][0] = fmaf(__low2float(d0),  SC2DN, accf[j][0]);
                accf[j][1] = fmaf(__high2float(d0), SC2DN, accf[j][1]);
                accf[j][2] = fmaf(__low2float(d1),  SC2DN, accf[j][2]);
                accf[j][3] = fmaf(__high2float(d1), SC2DN, accf[j][3]);
                acc2[j][0] = 0u; acc2[j][1] = 0u;
            }
        }
    }

    // epilogue: sigmoid + threefry bernoulli
    const int r4 = lane >> 2;
    const int c2 = (lane & 3) * 2;
#pragma unroll
    for (int ni = 0; ni < 4; ni++) {
        const float* c = accf[ni];
        const int col = bn + ni * 8 + c2;
        const int row = bm + wid * 16 + r4;
        const float cv0 = cvec[col], cv1 = cvec[col + 1];
#pragma unroll
        for (int half_ = 0; half_ < 2; half_++) {
            const int rr = row + half_ * 8;
            float x0 = __fadd_rn(c[half_ * 2 + 0], cv0);
            float x1 = __fadd_rn(c[half_ * 2 + 1], cv1);
            float p0 = __fadd_rn(__fmul_rn(0.5f, tanhf(__fmul_rn(0.5f, x0))), 0.5f);
            float p1 = __fadd_rn(__fmul_rn(0.5f, tanhf(__fmul_rn(0.5f, x1))), 0.5f);
            uint32_t gi = (uint32_t)rr * NH + col;
            float u0 = bits_to_unit(rand_bits(key0, key1, gi));
            float u1 = bits_to_unit(rand_bits(key0, key1, gi + 1));
            uint32_t b0 = (u0 < p0) ? 0x3C00u : 0u;   // fp16 1.0
            uint32_t b1 = (u1 < p1) ? 0x3C00u : 0u;
            *(uint32_t*)(g_hb + (size_t)rr * NH + col) = (b1 << 16) | b0;
            if (fout)
                *(float2*)(fout + (size_t)rr * NH + col) =
                    make_float2(b0 ? 1.0f : 0.0f, b1 ? 1.0f : 0.0f);
        }
    }
}

// ============ sample_v GEMM + fused gumbel-argmax categorical (BN=80, R9) ============
#define BM 128
#define BK 32
#define ROWB 80
#define ATILE (BM * ROWB)              // 10240
#define BNV 80
#define BTILEV (BNV * ROWB)            // 6400
#define STGV (ATILE + 2 * BTILEV)      // 23040
#define SMEMV (3 * STGV)               // 69120
#define TS 84
#define BSPLITV ((size_t)NCV * NH)

template<int WRITE_OUT>
__global__ __launch_bounds__(256, 3)
void k_mma_v(const __half* __restrict__ Asrc,   // g_hb, lda = NH
             const __half* __restrict__ Bsrc,   // g_Wv2, rows v*5+c, ldb = NH
             uint32_t key0, uint32_t key1,
             const float* __restrict__ bvec,
             float* __restrict__ vout) {
    extern __shared__ char smem[];
    const uint32_t sb = smem_u32(smem);
    float* tile = (float*)smem;
    const int tid = threadIdx.x;
    const int lane = tid & 31;
    const int wid = tid >> 5;          // 8 warps, each M=16 rows, full N=80
    const int bn = blockIdx.x * BNV;
    const int bm = blockIdx.y * BM;
    const int nk = NH / BK;            // 8

    const int ar0 = tid >> 2;
    const int ac  = (tid & 3) * 16;
    const int ack = (tid & 3) * 8;

    const uint32_t aoff = (uint32_t)((wid * 16 + (lane & 15)) * ROWB + (lane >> 4) * 16);
    const uint32_t boff = (uint32_t)(((lane & 7) + ((lane >> 4) << 3)) * ROWB
                                     + ((lane >> 3) & 1) * 16);

    auto issue = [&](int kc) {
        const int k0 = kc * BK;
        uint32_t s = sb + (kc % 3) * STGV;
        cp16(s + ar0 * ROWB + ac,        Asrc + (size_t)(bm + ar0) * NH + k0 + ack);
        cp16(s + (ar0 + 64) * ROWB + ac, Asrc + (size_t)(bm + ar0 + 64) * NH + k0 + ack);
#pragma unroll
        for (int sp = 0; sp < 2; sp++) {
#pragma unroll
            for (int i = 0; i < 2; i++) {
                int slot = tid + 256 * i;
                if (slot < 4 * BNV) {
                    int row = slot >> 2, col16 = (slot & 3) * 16;
                    cp16(s + ATILE + sp * BTILEV + row * ROWB + col16,
                         Bsrc + sp * BSPLITV + (size_t)(bn + row) * NH + k0 + (slot & 3) * 8);
                }
            }
        }
    };

    float acc[10][4];
#pragma unroll
    for (int j = 0; j < 10; j++)
#pragma unroll
        for (int q = 0; q < 4; q++) acc[j][q] = 0.0f;

    issue(0); CP_COMMIT();
    issue(1); CP_COMMIT();

#pragma unroll 1
    for (int kc = 0; kc < nk; kc++) {
        CP_WAIT(1);
        __syncthreads();
        if (kc + 2 < nk) issue(kc + 2);
        CP_COMMIT();

        const uint32_t sA = sb + (kc % 3) * STGV;
        const uint32_t sB = sA + ATILE;
#pragma unroll
        for (int ks = 0; ks < 2; ks++) {
            uint32_t a[4];
            ldmx4(a, sA + aoff + (uint32_t)(ks * 32));
#pragma unroll
            for (int sp = 0; sp < 2; sp++) {
#pragma unroll
                for (int g = 0; g < 5; g++) {
                    uint32_t b[4];
                    ldmx4(b, sB + sp * BTILEV + boff
                             + (uint32_t)(g * 16 * ROWB + ks * 32));
                    mma16816(acc[g * 2 + 0], a, b[0], b[1]);
                    mma16816(acc[g * 2 + 1], a, b[2], b[3]);
                }
            }
        }
    }

    // ---- epilogue: acc -> smem fp32 tile -> gumbel argmax over c ----
    __syncthreads();
    const int r4 = lane >> 2;
    const int c2 = (lane & 3) * 2;
    const int rw = wid * 16 + r4;
#pragma unroll
    for (int g = 0; g < 10; g++) {
        int col = g * 8 + c2;
        *(float2*)(tile + rw * TS + col)       = make_float2(acc[g][0], acc[g][1]);
        *(float2*)(tile + (rw + 8) * TS + col) = make_float2(acc[g][2], acc[g][3]);
    }
    __syncthreads();

    const int v0g = blockIdx.x * 16;
#pragma unroll 1
    for (int j = 0; j < 8; j++) {
        int idx = tid + 256 * j;
        int r  = idx >> 4;
        int vl = idx & 15;
        int bg = bm + r;
        int vg = v0g + vl;
        float best = 0.0f;
        uint32_t bc = 0;
#pragma unroll
        for (int c = 0; c < NC; c++) {
            float l = __fadd_rn(tile[r * TS + vl * NC + c], bvec[c * NV + vg]);
            uint32_t gi = (((uint32_t)bg * NC + (uint32_t)c) << 9) + (uint32_t)vg;
            float u = bits_to_unit(rand_bits(key0, key1, gi));
            float up = fmaxf(__fadd_rn(u, TINYF), TINYF);
            float gmb = -logf(-logf(up));
            float s = __fadd_rn(gmb, l);
            if (c == 0 || s > best) { best = s; bc = (uint32_t)c; }
        }
#pragma unroll
        for (int c = 0; c < NC; c++)
            g_A[(size_t)bg * NCV + c * NV + vg] =
                __ushort_as_half((c == (int)bc) ? (unsigned short)0x3C00u : (unsigned short)0u);
        if (WRITE_OUT) {
#pragma unroll
            for (int c = 0; c < NC; c++)
                vout[(size_t)bg * NCV + c * NV + vg] = (c == (int)bc) ? 1.0f : 0.0f;
        }
    }
}

// ---------------- launcher ----------------
extern "C" void kernel_launch(void* const* d_in, const int* in_sizes, int n_in,
                              void* d_out, int out_size) {
    const float* v0 = (const float*)d_in[0];
    const float* W  = (const float*)d_in[1];
    const float* bb = (const float*)d_in[2];
    const float* cc = (const float*)d_in[3];
    (void)in_sizes; (void)n_in; (void)out_size;

    float* out    = (float*)d_out;
    float* out_v  = out;
    float* out_h  = out + (size_t)NBCV;
    float* out_h0 = out_h + (size_t)NBH;

    uint32_t keys[5][2];
    for (uint32_t i = 0; i < 5; i++)
        threefry(0u, 42u, 0u, i, keys[i][0], keys[i][1]);

    cudaFuncSetAttribute(k_mma_h,    cudaFuncAttributeMaxDynamicSharedMemorySize, SMEMH);
    cudaFuncSetAttribute(k_mma_v<0>, cudaFuncAttributeMaxDynamicSharedMemorySize, SMEMV);
    cudaFuncSetAttribute(k_mma_v<1>, cudaFuncAttributeMaxDynamicSharedMemorySize, SMEMV);

    void *pA, *pHB, *pWv, *pWh;
    cudaGetSymbolAddress(&pA, g_A);
    cudaGetSymbolAddress(&pHB, g_hb);
    cudaGetSymbolAddress(&pWv, g_Wv2);
    cudaGetSymbolAddress(&pWh, g_Wh2);
    const __half* A   = (const __half*)pA;
    const __half* HB  = (const __half*)pHB;
    const __half* Wv2 = (const __half*)pWv;
    const __half* Wh2 = (const __half*)pWh;

    dim3 gh(NH / BNH, NB / BMH);    // (8, 128)
    dim3 gv(NCV / BNV, NB / BM);    // (32, 128)

    k_prep_wv<<<NCV * NH / 256, 256>>>(W);
    k_prep_wh<<<dim3(NCV / 256, NH), 256>>>(W);
    k_cast_A0<<<NBCV / 1024, 256>>>(v0);

    // h = sample_h(keys[0], v0) -> out_h0
    k_mma_h<<<gh, 256, SMEMH>>>(A, Wh2, keys[0][0], keys[0][1], cc, out_h0);
    // iter 0
    k_mma_v<0><<<gv, 256, SMEMV>>>(HB, Wv2, keys[1][0], keys[1][1], bb, nullptr);
    k_mma_h<<<gh, 256, SMEMH>>>(A, Wh2, keys[2][0], keys[2][1], cc, nullptr);
    // iter 1
    k_mma_v<1><<<gv, 256, SMEMV>>>(HB, Wv2, keys[3][0], keys[3][1], bb, out_v);
    k_mma_h<<<gh, 256, SMEMH>>>(A, Wh2, keys[4][0], keys[4][1], cc, out_h);
}